// round 11
// baseline (speedup 1.0000x reference)
#include <cuda_runtime.h>

#define B_ 4096
#define T_ 256
#define C_ 64
#define H_ 16
#define D_ 16
#define S_ 10
#define TO_ 255

// PLANAR xw: plane j at g_xw[j*B*T + b*T + t]  (lane streams contiguous in t)
__device__ float g_xw[(long)H_ * B_ * T_];
__device__ float g_hs[(long)B_ * T_ * H_];   // RNN hidden states, row-major [r][16]
// PLANAR tr: plane j at g_tr[j*B*T + b*T + (t-1)], t in [1,256)
__device__ float g_tr[(long)10 * B_ * T_];

// ---- fast transcendentals ----
__device__ __forceinline__ float fex2(float x) {
    float r; asm("ex2.approx.f32 %0, %1;" : "=f"(r) : "f"(x)); return r;
}
__device__ __forceinline__ float frcp(float x) {
    float r; asm("rcp.approx.f32 %0, %1;" : "=f"(r) : "f"(x)); return r;
}
__device__ __forceinline__ float fsig(float x) {
    return frcp(1.0f + fex2(-1.4426950408889634f * x));
}
__device__ __forceinline__ float ftanh(float x) {
    return fmaf(2.0f, frcp(1.0f + fex2(-2.8853900817779268f * x)), -1.0f);
}

// ---------------------------------------------------------------------------
// Kernel 1: fused LayerNorm + x@Wx + b (LN folded). ONE row per thread,
// full-row BURST load (16 back-to-back LDG.128, MLP=16) so DRAM latency is
// overlapped once per row instead of exposed 16x per row.
// ---------------------------------------------------------------------------
__global__ void __launch_bounds__(256) k_ln_xw(
    const float* __restrict__ cov,
    const float* __restrict__ gamma,
    const float* __restrict__ beta,
    const float* __restrict__ wx,
    const float* __restrict__ rnn_b)
{
    __shared__ float sWg[C_ * H_];
    __shared__ float sS1[H_];
    __shared__ float sS2[H_];

    int tid = threadIdx.x;
    for (int i = tid; i < C_ * H_; i += blockDim.x) {
        int c = i >> 4;
        sWg[i] = gamma[c] * wx[i];
    }
    __syncthreads();
    if (tid < H_) {
        float s1 = 0.f, s2 = 0.f;
        for (int c = 0; c < C_; c++) {
            s1 += sWg[c * H_ + tid];
            s2 += beta[c] * wx[c * H_ + tid];
        }
        sS1[tid] = s1;
        sS2[tid] = s2 + rnn_b[tid];
    }
    __syncthreads();

    const float4* wg4 = reinterpret_cast<const float4*>(sWg);
    const long BT = (long)B_ * T_;

    long r = (long)blockIdx.x * blockDim.x + tid;

    // ---- burst load: entire row into registers (16 independent LDG.128) ----
    const float4* cv = reinterpret_cast<const float4*>(cov + r * C_);
    float4 xv[16];
#pragma unroll
    for (int i = 0; i < 16; i++) xv[i] = cv[i];
    const float* xs = reinterpret_cast<const float*>(xv);

    // ---- LN stats from registers ----
    float sum = 0.f, sq = 0.f;
#pragma unroll
    for (int i = 0; i < 16; i++) {
        float4 v = xv[i];
        sum += v.x + v.y + v.z + v.w;
        sq = fmaf(v.x, v.x, sq);
        sq = fmaf(v.y, v.y, sq);
        sq = fmaf(v.z, v.z, sq);
        sq = fmaf(v.w, v.w, sq);
    }

    // ---- GEMM row x Wg from registers + broadcast LDS ----
    float acc[H_];
#pragma unroll
    for (int j = 0; j < H_; j++) acc[j] = 0.f;

#pragma unroll
    for (int c = 0; c < C_; c++) {
        float x = xs[c];
        float4 w0 = wg4[c * 4 + 0];
        float4 w1 = wg4[c * 4 + 1];
        float4 w2 = wg4[c * 4 + 2];
        float4 w3 = wg4[c * 4 + 3];
        acc[0]  = fmaf(x, w0.x, acc[0]);  acc[1]  = fmaf(x, w0.y, acc[1]);
        acc[2]  = fmaf(x, w0.z, acc[2]);  acc[3]  = fmaf(x, w0.w, acc[3]);
        acc[4]  = fmaf(x, w1.x, acc[4]);  acc[5]  = fmaf(x, w1.y, acc[5]);
        acc[6]  = fmaf(x, w1.z, acc[6]);  acc[7]  = fmaf(x, w1.w, acc[7]);
        acc[8]  = fmaf(x, w2.x, acc[8]);  acc[9]  = fmaf(x, w2.y, acc[9]);
        acc[10] = fmaf(x, w2.z, acc[10]); acc[11] = fmaf(x, w2.w, acc[11]);
        acc[12] = fmaf(x, w3.x, acc[12]); acc[13] = fmaf(x, w3.y, acc[13]);
        acc[14] = fmaf(x, w3.z, acc[14]); acc[15] = fmaf(x, w3.w, acc[15]);
    }

    float mu = sum * (1.f/64.f);
    float rs = rsqrtf(sq * (1.f/64.f) - mu*mu + 1e-3f);
    float rm = rs * mu;

    // planar stores (coalesced per plane across the warp)
#pragma unroll
    for (int j = 0; j < H_; j++)
        g_xw[j * BT + r] = rs * acc[j] - rm * sS1[j] + sS2[j];
}

// ---------------------------------------------------------------------------
// Kernel 2: RNN recurrence. 16-lane team per batch, 2 teams/warp.
// Planar xw: lane streams its plane contiguously in t; 8 steps per two
// float4 loads, double-buffered.
// ---------------------------------------------------------------------------
__global__ void __launch_bounds__(128) k_rnn(const float* __restrict__ wh)
{
    const unsigned FULL = 0xffffffffu;
    int tid = threadIdx.x;
    int q = tid & 15;
    int b = blockIdx.x * 8 + (tid >> 4);

    float whc[H_];
#pragma unroll
    for (int i = 0; i < H_; i++) whc[i] = wh[i * H_ + q];

    const long BT = (long)B_ * T_;
    const float4* xp = reinterpret_cast<const float4*>(g_xw + (long)q * BT + (long)b * T_);
    float* hsp = g_hs + (long)b * T_ * H_;

    float h = 0.f;
    float4 c0 = xp[0], c1 = xp[1];

    for (int t8 = 0; t8 < T_ / 8; t8++) {
        float4 n0, n1;
        if (t8 + 1 < T_ / 8) {
            n0 = xp[(t8 + 1) * 2];
            n1 = xp[(t8 + 1) * 2 + 1];
        } else {
            n0 = make_float4(0.f, 0.f, 0.f, 0.f);
            n1 = n0;
        }
        float xw8[8] = {c0.x, c0.y, c0.z, c0.w, c1.x, c1.y, c1.z, c1.w};
#pragma unroll
        for (int u = 0; u < 8; u++) {
            float a0 = xw8[u], a1 = 0.f, a2 = 0.f, a3 = 0.f;
#pragma unroll
            for (int i = 0; i < H_; i += 4) {
                a0 = fmaf(__shfl_sync(FULL, h, i,     16), whc[i],     a0);
                a1 = fmaf(__shfl_sync(FULL, h, i + 1, 16), whc[i + 1], a1);
                a2 = fmaf(__shfl_sync(FULL, h, i + 2, 16), whc[i + 2], a2);
                a3 = fmaf(__shfl_sync(FULL, h, i + 3, 16), whc[i + 3], a3);
            }
            h = ftanh((a0 + a1) + (a2 + a3));
            hsp[(t8 * 8 + u) * H_ + q] = h;
        }
        c0 = n0; c1 = n1;
    }
}

// ---------------------------------------------------------------------------
// Kernel 3: batched driver MLP + transforms. Planar coalesced output.
// ---------------------------------------------------------------------------
__global__ void __launch_bounds__(256) k_mlp(
    const float* __restrict__ d1w,
    const float* __restrict__ d1b,
    const float* __restrict__ d2w,
    const float* __restrict__ d2b)
{
    __shared__ float sw1[H_ * H_];
    __shared__ float sw2[H_ * 10];
    __shared__ float sb1[H_];
    __shared__ float sb2[10];

    int tid = threadIdx.x;
    if (tid < H_ * H_) sw1[tid] = d1w[tid];
    if (tid < H_ * 10) { int i = tid / 10, j = tid % 10; sw2[tid] = d2w[i * D_ + j]; }
    if (tid < H_) sb1[tid] = d1b[tid];
    if (tid < 10) sb2[tid] = d2b[tid];
    __syncthreads();

    long r = (long)blockIdx.x * blockDim.x + tid;
    int t = (int)(r & (T_ - 1));
    if (t == 0) return;   // drivers for t=0 unused

    const float4* hp = reinterpret_cast<const float4*>(g_hs + r * H_);
    float4 h4[4] = {hp[0], hp[1], hp[2], hp[3]};
    const float* hv = reinterpret_cast<const float*>(h4);

    const float4* w14 = reinterpret_cast<const float4*>(sw1);
    float a[H_];
#pragma unroll
    for (int j = 0; j < H_; j++) a[j] = sb1[j];
#pragma unroll
    for (int i = 0; i < H_; i++) {
        float xi = hv[i];
        float4 w0 = w14[i * 4 + 0];
        float4 w1 = w14[i * 4 + 1];
        float4 w2 = w14[i * 4 + 2];
        float4 w3 = w14[i * 4 + 3];
        a[0]  += xi * w0.x; a[1]  += xi * w0.y; a[2]  += xi * w0.z; a[3]  += xi * w0.w;
        a[4]  += xi * w1.x; a[5]  += xi * w1.y; a[6]  += xi * w1.z; a[7]  += xi * w1.w;
        a[8]  += xi * w2.x; a[9]  += xi * w2.y; a[10] += xi * w2.z; a[11] += xi * w2.w;
        a[12] += xi * w3.x; a[13] += xi * w3.y; a[14] += xi * w3.z; a[15] += xi * w3.w;
    }
#pragma unroll
    for (int j = 0; j < H_; j++) a[j] = ftanh(a[j]);

    float d[10];
#pragma unroll
    for (int j = 0; j < 10; j++) d[j] = sb2[j];
#pragma unroll
    for (int i = 0; i < H_; i++) {
        float xi = a[i];
        const float2* w2r = reinterpret_cast<const float2*>(sw2 + i * 10);
#pragma unroll
        for (int j2 = 0; j2 < 5; j2++) {
            float2 w = w2r[j2];
            d[j2 * 2]     += xi * w.x;
            d[j2 * 2 + 1] += xi * w.y;
        }
    }

    const long BT = (long)B_ * T_;
    float* p = g_tr + (r - 1);     // stored at index t-1 within batch row
    p[0 * BT] = fsig(2.0f * d[0]) * 0.4f - 0.2f;   // tanh(d0)*0.2
    p[1 * BT] = fsig(d[1]);
    p[2 * BT] = fsig(d[2]) * 0.5f;
    p[3 * BT] = fsig(d[3]) * 0.1f;
    p[4 * BT] = fsig(d[4]) * 0.2f;
    p[5 * BT] = fsig(d[5]);
    p[6 * BT] = fsig(d[6]);
    p[7 * BT] = fsig(d[7]);
    p[8 * BT] = fsig(d[8]) * 0.35f;
    p[9 * BT] = fsig(d[9]) * 0.1f;
}

// ---------------------------------------------------------------------------
// Kernel 4: cash-budget scan. T-parallel, one warp per batch.
// ---------------------------------------------------------------------------
#define SKW(i) ((i) + ((i) >> 5))
#define STG_W 2632
#define ISG_W 1844

__global__ void __launch_bounds__(128) k_cash(
    const float* __restrict__ states_seq,
    float* __restrict__ out)
{
    __shared__ float sbuf[4 * STG_W];   // 42 KB, reused for both passes

    const unsigned FULL = 0xffffffffu;
    int lane = threadIdx.x & 31;
    int w = threadIdx.x >> 5;
    int b = blockIdx.x * 4 + w;
    int o0 = lane * 8;
    int n = (lane == 31) ? 7 : 8;

    const float* s0 = states_seq + (long)b * T_ * S_;
    float s0rev = s0[0], s0cash = s0[1], s0ar = s0[2], s0inv = s0[3], s0ppe = s0[4],
          s0ap  = s0[5], debt = s0[6], eqty = s0[7], s0re = s0[8], oth = s0[9];

    const long BT = (long)B_ * T_;
    float tr[8][10];
    {
        const float* base = g_tr + (long)b * T_ + o0;
#pragma unroll
        for (int j = 0; j < 10; j++) {
            float4 v0 = *reinterpret_cast<const float4*>(base + j * BT);
            float4 v1 = *reinterpret_cast<const float4*>(base + j * BT + 4);
            tr[0][j] = v0.x; tr[1][j] = v0.y; tr[2][j] = v0.z; tr[3][j] = v0.w;
            tr[4][j] = v1.x; tr[5][j] = v1.y; tr[6][j] = v1.z; tr[7][j] = v1.w;
        }
    }

    // ---- phase 1: revenue product scan ----
    float Pg = 1.f;
#pragma unroll
    for (int k = 0; k < 8; k++) if (k < n) Pg *= (1.f + tr[k][0]);
    float p = Pg;
#pragma unroll
    for (int dd = 1; dd < 32; dd <<= 1) {
        float v = __shfl_up_sync(FULL, p, dd);
        if (lane >= dd) p *= v;
    }
    float pe = __shfl_up_sync(FULL, p, 1);
    if (lane == 0) pe = 1.f;
    float revS = s0rev * pe;

    // ---- phase 2: rev stepwise + ppe affine scan ----
    float rev[8];
    float A = 1.f, Bc = 0.f, rprev = revS;
#pragma unroll
    for (int k = 0; k < 8; k++) {
        if (k < n) {
            rprev *= (1.f + tr[k][0]);
            rev[k] = rprev;
            float om = 1.f - tr[k][3];
            A = A * om;
            Bc = fmaf(Bc, om, tr[k][4] * rprev);
        } else rev[k] = rprev;
    }
    float a_ = A, b_ = Bc;
#pragma unroll
    for (int dd = 1; dd < 32; dd <<= 1) {
        float av = __shfl_up_sync(FULL, a_, dd);
        float bv = __shfl_up_sync(FULL, b_, dd);
        if (lane >= dd) { b_ = fmaf(bv, a_, b_); a_ = av * a_; }
    }
    float aex = __shfl_up_sync(FULL, a_, 1);
    float bex = __shfl_up_sync(FULL, b_, 1);
    if (lane == 0) { aex = 1.f; bex = 0.f; }
    float ppeS = fmaf(aex, s0ppe, bex);

    // ---- chunk-boundary lagged ar/inv/ap ----
    float pr1 = __shfl_up_sync(FULL, tr[7][1], 1);
    float pr5 = __shfl_up_sync(FULL, tr[7][5], 1);
    float pr6 = __shfl_up_sync(FULL, tr[7][6], 1);
    float pr7 = __shfl_up_sync(FULL, tr[7][7], 1);
    float arP, invP, apP;
    if (lane == 0) { arP = s0ar; invP = s0inv; apP = s0ap; }
    else {
        float cogsP = pr1 * revS;
        arP = pr5 * revS; invP = pr6 * cogsP; apP = pr7 * cogsP;
    }

    // ---- phase 3: chunk sums of cash & re increments ----
    float Cs = 0.f, Rs = 0.f;
    {
        float ppeP = ppeS, arp = arP, invp = invP, app = apP;
#pragma unroll
        for (int k = 0; k < 8; k++) {
            if (k < n) {
                float nrev = rev[k];
                float cogs = tr[k][1] * nrev;
                float opex = tr[k][2] * nrev;
                float dep  = tr[k][3] * ppeP;
                float intr = tr[k][9] * debt;
                float ebt  = nrev - cogs - opex - dep - intr;
                float tax  = tr[k][8] * fmaxf(ebt, 0.f);
                float ni   = ebt - tax;
                float arn  = tr[k][5] * nrev;
                float invn = tr[k][6] * cogs;
                float apn  = tr[k][7] * cogs;
                float capex = tr[k][4] * nrev;
                float cinc = ni + dep - capex - (arn - arp) - (invn - invp) + (apn - app);
                Cs += cinc; Rs += ni;
                ppeP = ppeP + capex - dep;
                arp = arn; invp = invn; app = apn;
            }
        }
    }
    float c = Cs;
#pragma unroll
    for (int dd = 1; dd < 32; dd <<= 1) {
        float v = __shfl_up_sync(FULL, c, dd);
        if (lane >= dd) c += v;
    }
    float ce = __shfl_up_sync(FULL, c, 1);
    if (lane == 0) ce = 0.f;
    float cashS = s0cash + ce;

    float rr = Rs;
#pragma unroll
    for (int dd = 1; dd < 32; dd <<= 1) {
        float v = __shfl_up_sync(FULL, rr, dd);
        if (lane >= dd) rr += v;
    }
    float re_e = __shfl_up_sync(FULL, rr, 1);
    if (lane == 0) re_e = 0.f;
    float reS = s0re + re_e;

    // ---- phase 4a: states walk -> skewed smem ----
    {
        float* sw = sbuf + w * STG_W;
        float cash = cashS, re = reS;
        float ppeP = ppeS, arp = arP, invp = invP, app = apP;
#pragma unroll
        for (int k = 0; k < 8; k++) {
            if (k < n) {
                float nrev = rev[k];
                float cogs = tr[k][1] * nrev;
                float opex = tr[k][2] * nrev;
                float dep  = tr[k][3] * ppeP;
                float intr = tr[k][9] * debt;
                float ebt  = nrev - cogs - opex - dep - intr;
                float tax  = tr[k][8] * fmaxf(ebt, 0.f);
                float ni   = ebt - tax;
                float arn  = tr[k][5] * nrev;
                float invn = tr[k][6] * cogs;
                float apn  = tr[k][7] * cogs;
                float capex = tr[k][4] * nrev;
                float ppen = ppeP + capex - dep;
                float cinc = ni + dep - capex - (arn - arp) - (invn - invp) + (apn - app);
                cash += cinc; re += ni;

                int idx = (o0 + k) * S_;
                sw[SKW(idx + 0)] = nrev;  sw[SKW(idx + 1)] = cash;
                sw[SKW(idx + 2)] = arn;   sw[SKW(idx + 3)] = invn;
                sw[SKW(idx + 4)] = ppen;  sw[SKW(idx + 5)] = apn;
                sw[SKW(idx + 6)] = debt;  sw[SKW(idx + 7)] = eqty;
                sw[SKW(idx + 8)] = re;    sw[SKW(idx + 9)] = oth;

                ppeP = ppen; arp = arn; invp = invn; app = apn;
            }
        }
    }
    __syncthreads();

    {
        int tid = threadIdx.x;
#pragma unroll
        for (int w2 = 0; w2 < 4; w2++) {
            const float* s = sbuf + w2 * STG_W;
            float* g = out + (long)(blockIdx.x * 4 + w2) * TO_ * S_;
            for (int i = tid; i < TO_ * S_; i += 128)
                g[i] = s[SKW(i)];
        }
    }
    __syncthreads();

    // ---- phase 4b: is walk -> skewed smem (reuse buffer) ----
    {
        float* sw = sbuf + w * ISG_W;
        float ppeP = ppeS, arp = arP, invp = invP, app = apP;
#pragma unroll
        for (int k = 0; k < 8; k++) {
            if (k < n) {
                float nrev = rev[k];
                float cogs = tr[k][1] * nrev;
                float opex = tr[k][2] * nrev;
                float dep  = tr[k][3] * ppeP;
                float intr = tr[k][9] * debt;
                float ebt  = nrev - cogs - opex - dep - intr;
                float tax  = tr[k][8] * fmaxf(ebt, 0.f);
                float ni   = ebt - tax;
                float capex = tr[k][4] * nrev;

                int idx = (o0 + k) * 7;
                sw[SKW(idx + 0)] = nrev;  sw[SKW(idx + 1)] = cogs;
                sw[SKW(idx + 2)] = opex;  sw[SKW(idx + 3)] = dep;
                sw[SKW(idx + 4)] = intr;  sw[SKW(idx + 5)] = tax;
                sw[SKW(idx + 6)] = ni;

                ppeP = ppeP + capex - dep;
                arp = tr[k][5] * nrev; invp = tr[k][6] * cogs; app = tr[k][7] * cogs;
            }
        }
    }
    __syncthreads();

    {
        int tid = threadIdx.x;
        float* ob = out + (long)B_ * TO_ * S_;
#pragma unroll
        for (int w2 = 0; w2 < 4; w2++) {
            const float* s = sbuf + w2 * ISG_W;
            float* g = ob + (long)(blockIdx.x * 4 + w2) * TO_ * 7;
            for (int i = tid; i < TO_ * 7; i += 128)
                g[i] = s[SKW(i)];
        }
    }
}

extern "C" void kernel_launch(void* const* d_in, const int* in_sizes, int n_in,
                              void* d_out, int out_size)
{
    const float* states = (const float*)d_in[0];
    const float* cov    = (const float*)d_in[1];
    const float* gamma  = (const float*)d_in[2];
    const float* beta   = (const float*)d_in[3];
    const float* wx     = (const float*)d_in[4];
    const float* wh     = (const float*)d_in[5];
    const float* rnn_b  = (const float*)d_in[6];
    const float* d1w    = (const float*)d_in[7];
    const float* d1b    = (const float*)d_in[8];
    const float* d2w    = (const float*)d_in[9];
    const float* d2b    = (const float*)d_in[10];
    float* out = (float*)d_out;

    k_ln_xw<<<(B_ * T_) / 256, 256>>>(cov, gamma, beta, wx, rnn_b);
    k_rnn<<<B_ / 8, 128>>>(wh);
    k_mlp<<<(B_ * T_) / 256, 256>>>(d1w, d1b, d2w, d2b);
    k_cash<<<B_ / 4, 128>>>(states, out);
}

// round 12
// speedup vs baseline: 1.0873x; 1.0873x over previous
#include <cuda_runtime.h>

#define B_ 4096
#define T_ 256
#define C_ 64
#define H_ 16
#define D_ 16
#define S_ 10
#define TO_ 255

// PLANAR xw: plane j at g_xw[j*B*T + b*T + t]  (lane streams contiguous in t)
__device__ float g_xw[(long)H_ * B_ * T_];
__device__ float g_hs[(long)B_ * T_ * H_];   // RNN hidden states, row-major [r][16]
// PLANAR tr: plane j at g_tr[j*B*T + b*T + (t-1)], t in [1,256)
__device__ float g_tr[(long)10 * B_ * T_];

// ---- fast transcendentals ----
__device__ __forceinline__ float fex2(float x) {
    float r; asm("ex2.approx.f32 %0, %1;" : "=f"(r) : "f"(x)); return r;
}
__device__ __forceinline__ float frcp(float x) {
    float r; asm("rcp.approx.f32 %0, %1;" : "=f"(r) : "f"(x)); return r;
}
__device__ __forceinline__ float fsig(float x) {
    return frcp(1.0f + fex2(-1.4426950408889634f * x));
}
__device__ __forceinline__ float ftanh(float x) {
    return fmaf(2.0f, frcp(1.0f + fex2(-2.8853900817779268f * x)), -1.0f);
}

// ---------------------------------------------------------------------------
// Kernel 1: fused LayerNorm + x@Wx + b (LN folded). 4 rows per thread
// (amortizes weight LDS), software-pipelined cov loads (prefetch distance 1)
// so the per-iteration load->use stall overlaps with the previous iteration's
// ~70 cycles of FMA issue. Planar output for k_rnn streaming.
// ---------------------------------------------------------------------------
__global__ void __launch_bounds__(256) k_ln_xw(
    const float* __restrict__ cov,
    const float* __restrict__ gamma,
    const float* __restrict__ beta,
    const float* __restrict__ wx,
    const float* __restrict__ rnn_b)
{
    __shared__ float sWg[C_ * H_];
    __shared__ float sS1[H_];
    __shared__ float sS2[H_];

    int tid = threadIdx.x;
    for (int i = tid; i < C_ * H_; i += blockDim.x) {
        int c = i >> 4;
        sWg[i] = gamma[c] * wx[i];
    }
    __syncthreads();
    if (tid < H_) {
        float s1 = 0.f, s2 = 0.f;
        for (int c = 0; c < C_; c++) {
            s1 += sWg[c * H_ + tid];
            s2 += beta[c] * wx[c * H_ + tid];
        }
        sS1[tid] = s1;
        sS2[tid] = s2 + rnn_b[tid];
    }
    __syncthreads();

    const float4* wg4 = reinterpret_cast<const float4*>(sWg);

    const long Q = (long)B_ * T_ / 4;
    const long BT = (long)B_ * T_;
    long r = (long)blockIdx.x * blockDim.x + tid;

    const float4* cv[4];
#pragma unroll
    for (int s = 0; s < 4; s++)
        cv[s] = reinterpret_cast<const float4*>(cov + (r + s * Q) * C_);

    float acc[4][H_];
#pragma unroll
    for (int s = 0; s < 4; s++)
#pragma unroll
        for (int j = 0; j < H_; j++) acc[s][j] = 0.f;
    float sum[4] = {0.f, 0.f, 0.f, 0.f};
    float sq[4]  = {0.f, 0.f, 0.f, 0.f};

    // software pipeline: prefetch distance 1
    float4 cur[4], nxt[4];
#pragma unroll
    for (int s = 0; s < 4; s++) cur[s] = cv[s][0];

    for (int c4 = 0; c4 < C_ / 4; c4++) {
        if (c4 + 1 < C_ / 4) {
#pragma unroll
            for (int s = 0; s < 4; s++) nxt[s] = cv[s][c4 + 1];
        }
        float xs[4][4];
#pragma unroll
        for (int s = 0; s < 4; s++) {
            xs[s][0] = cur[s].x; xs[s][1] = cur[s].y;
            xs[s][2] = cur[s].z; xs[s][3] = cur[s].w;
        }
#pragma unroll
        for (int k = 0; k < 4; k++) {
            int c = c4 * 4 + k;
            float4 w0 = wg4[c * 4 + 0];
            float4 w1 = wg4[c * 4 + 1];
            float4 w2 = wg4[c * 4 + 2];
            float4 w3 = wg4[c * 4 + 3];
#pragma unroll
            for (int s = 0; s < 4; s++) {
                float x = xs[s][k];
                sum[s] += x;
                sq[s] = fmaf(x, x, sq[s]);
                acc[s][0]  += x * w0.x; acc[s][1]  += x * w0.y;
                acc[s][2]  += x * w0.z; acc[s][3]  += x * w0.w;
                acc[s][4]  += x * w1.x; acc[s][5]  += x * w1.y;
                acc[s][6]  += x * w1.z; acc[s][7]  += x * w1.w;
                acc[s][8]  += x * w2.x; acc[s][9]  += x * w2.y;
                acc[s][10] += x * w2.z; acc[s][11] += x * w2.w;
                acc[s][12] += x * w3.x; acc[s][13] += x * w3.y;
                acc[s][14] += x * w3.z; acc[s][15] += x * w3.w;
            }
        }
#pragma unroll
        for (int s = 0; s < 4; s++) cur[s] = nxt[s];
    }

#pragma unroll
    for (int s = 0; s < 4; s++) {
        float mu = sum[s] * (1.f/64.f);
        float rs = rsqrtf(sq[s] * (1.f/64.f) - mu*mu + 1e-3f);
        float rm = rs * mu;
        long rr = r + s * Q;
#pragma unroll
        for (int j = 0; j < H_; j++)
            g_xw[j * BT + rr] = rs * acc[s][j] - rm * sS1[j] + sS2[j];
    }
}

// ---------------------------------------------------------------------------
// Kernel 2: RNN recurrence. 16-lane team per batch, 2 teams/warp.
// Planar xw: lane streams its plane contiguously in t; 8 steps per two
// float4 loads, double-buffered.
// ---------------------------------------------------------------------------
__global__ void __launch_bounds__(128) k_rnn(const float* __restrict__ wh)
{
    const unsigned FULL = 0xffffffffu;
    int tid = threadIdx.x;
    int q = tid & 15;
    int b = blockIdx.x * 8 + (tid >> 4);

    float whc[H_];
#pragma unroll
    for (int i = 0; i < H_; i++) whc[i] = wh[i * H_ + q];

    const long BT = (long)B_ * T_;
    const float4* xp = reinterpret_cast<const float4*>(g_xw + (long)q * BT + (long)b * T_);
    float* hsp = g_hs + (long)b * T_ * H_;

    float h = 0.f;
    float4 c0 = xp[0], c1 = xp[1];

    for (int t8 = 0; t8 < T_ / 8; t8++) {
        float4 n0, n1;
        if (t8 + 1 < T_ / 8) {
            n0 = xp[(t8 + 1) * 2];
            n1 = xp[(t8 + 1) * 2 + 1];
        } else {
            n0 = make_float4(0.f, 0.f, 0.f, 0.f);
            n1 = n0;
        }
        float xw8[8] = {c0.x, c0.y, c0.z, c0.w, c1.x, c1.y, c1.z, c1.w};
#pragma unroll
        for (int u = 0; u < 8; u++) {
            float a0 = xw8[u], a1 = 0.f, a2 = 0.f, a3 = 0.f;
#pragma unroll
            for (int i = 0; i < H_; i += 4) {
                a0 = fmaf(__shfl_sync(FULL, h, i,     16), whc[i],     a0);
                a1 = fmaf(__shfl_sync(FULL, h, i + 1, 16), whc[i + 1], a1);
                a2 = fmaf(__shfl_sync(FULL, h, i + 2, 16), whc[i + 2], a2);
                a3 = fmaf(__shfl_sync(FULL, h, i + 3, 16), whc[i + 3], a3);
            }
            h = ftanh((a0 + a1) + (a2 + a3));
            hsp[(t8 * 8 + u) * H_ + q] = h;
        }
        c0 = n0; c1 = n1;
    }
}

// ---------------------------------------------------------------------------
// Kernel 3: batched driver MLP + transforms. Planar coalesced output.
// ---------------------------------------------------------------------------
__global__ void __launch_bounds__(256) k_mlp(
    const float* __restrict__ d1w,
    const float* __restrict__ d1b,
    const float* __restrict__ d2w,
    const float* __restrict__ d2b)
{
    __shared__ float sw1[H_ * H_];
    __shared__ float sw2[H_ * 10];
    __shared__ float sb1[H_];
    __shared__ float sb2[10];

    int tid = threadIdx.x;
    if (tid < H_ * H_) sw1[tid] = d1w[tid];
    if (tid < H_ * 10) { int i = tid / 10, j = tid % 10; sw2[tid] = d2w[i * D_ + j]; }
    if (tid < H_) sb1[tid] = d1b[tid];
    if (tid < 10) sb2[tid] = d2b[tid];
    __syncthreads();

    long r = (long)blockIdx.x * blockDim.x + tid;
    int t = (int)(r & (T_ - 1));
    if (t == 0) return;   // drivers for t=0 unused

    const float4* hp = reinterpret_cast<const float4*>(g_hs + r * H_);
    float4 h4[4] = {hp[0], hp[1], hp[2], hp[3]};
    const float* hv = reinterpret_cast<const float*>(h4);

    const float4* w14 = reinterpret_cast<const float4*>(sw1);
    float a[H_];
#pragma unroll
    for (int j = 0; j < H_; j++) a[j] = sb1[j];
#pragma unroll
    for (int i = 0; i < H_; i++) {
        float xi = hv[i];
        float4 w0 = w14[i * 4 + 0];
        float4 w1 = w14[i * 4 + 1];
        float4 w2 = w14[i * 4 + 2];
        float4 w3 = w14[i * 4 + 3];
        a[0]  += xi * w0.x; a[1]  += xi * w0.y; a[2]  += xi * w0.z; a[3]  += xi * w0.w;
        a[4]  += xi * w1.x; a[5]  += xi * w1.y; a[6]  += xi * w1.z; a[7]  += xi * w1.w;
        a[8]  += xi * w2.x; a[9]  += xi * w2.y; a[10] += xi * w2.z; a[11] += xi * w2.w;
        a[12] += xi * w3.x; a[13] += xi * w3.y; a[14] += xi * w3.z; a[15] += xi * w3.w;
    }
#pragma unroll
    for (int j = 0; j < H_; j++) a[j] = ftanh(a[j]);

    float d[10];
#pragma unroll
    for (int j = 0; j < 10; j++) d[j] = sb2[j];
#pragma unroll
    for (int i = 0; i < H_; i++) {
        float xi = a[i];
        const float2* w2r = reinterpret_cast<const float2*>(sw2 + i * 10);
#pragma unroll
        for (int j2 = 0; j2 < 5; j2++) {
            float2 w = w2r[j2];
            d[j2 * 2]     += xi * w.x;
            d[j2 * 2 + 1] += xi * w.y;
        }
    }

    const long BT = (long)B_ * T_;
    float* p = g_tr + (r - 1);     // stored at index t-1 within batch row
    p[0 * BT] = fsig(2.0f * d[0]) * 0.4f - 0.2f;   // tanh(d0)*0.2
    p[1 * BT] = fsig(d[1]);
    p[2 * BT] = fsig(d[2]) * 0.5f;
    p[3 * BT] = fsig(d[3]) * 0.1f;
    p[4 * BT] = fsig(d[4]) * 0.2f;
    p[5 * BT] = fsig(d[5]);
    p[6 * BT] = fsig(d[6]);
    p[7 * BT] = fsig(d[7]);
    p[8 * BT] = fsig(d[8]) * 0.35f;
    p[9 * BT] = fsig(d[9]) * 0.1f;
}

// ---------------------------------------------------------------------------
// Kernel 4: cash-budget scan. T-parallel, one warp per batch.
// ---------------------------------------------------------------------------
#define SKW(i) ((i) + ((i) >> 5))
#define STG_W 2632
#define ISG_W 1844

__global__ void __launch_bounds__(128) k_cash(
    const float* __restrict__ states_seq,
    float* __restrict__ out)
{
    __shared__ float sbuf[4 * STG_W];   // 42 KB, reused for both passes

    const unsigned FULL = 0xffffffffu;
    int lane = threadIdx.x & 31;
    int w = threadIdx.x >> 5;
    int b = blockIdx.x * 4 + w;
    int o0 = lane * 8;
    int n = (lane == 31) ? 7 : 8;

    const float* s0 = states_seq + (long)b * T_ * S_;
    float s0rev = s0[0], s0cash = s0[1], s0ar = s0[2], s0inv = s0[3], s0ppe = s0[4],
          s0ap  = s0[5], debt = s0[6], eqty = s0[7], s0re = s0[8], oth = s0[9];

    const long BT = (long)B_ * T_;
    float tr[8][10];
    {
        const float* base = g_tr + (long)b * T_ + o0;
#pragma unroll
        for (int j = 0; j < 10; j++) {
            float4 v0 = *reinterpret_cast<const float4*>(base + j * BT);
            float4 v1 = *reinterpret_cast<const float4*>(base + j * BT + 4);
            tr[0][j] = v0.x; tr[1][j] = v0.y; tr[2][j] = v0.z; tr[3][j] = v0.w;
            tr[4][j] = v1.x; tr[5][j] = v1.y; tr[6][j] = v1.z; tr[7][j] = v1.w;
        }
    }

    // ---- phase 1: revenue product scan ----
    float Pg = 1.f;
#pragma unroll
    for (int k = 0; k < 8; k++) if (k < n) Pg *= (1.f + tr[k][0]);
    float p = Pg;
#pragma unroll
    for (int dd = 1; dd < 32; dd <<= 1) {
        float v = __shfl_up_sync(FULL, p, dd);
        if (lane >= dd) p *= v;
    }
    float pe = __shfl_up_sync(FULL, p, 1);
    if (lane == 0) pe = 1.f;
    float revS = s0rev * pe;

    // ---- phase 2: rev stepwise + ppe affine scan ----
    float rev[8];
    float A = 1.f, Bc = 0.f, rprev = revS;
#pragma unroll
    for (int k = 0; k < 8; k++) {
        if (k < n) {
            rprev *= (1.f + tr[k][0]);
            rev[k] = rprev;
            float om = 1.f - tr[k][3];
            A = A * om;
            Bc = fmaf(Bc, om, tr[k][4] * rprev);
        } else rev[k] = rprev;
    }
    float a_ = A, b_ = Bc;
#pragma unroll
    for (int dd = 1; dd < 32; dd <<= 1) {
        float av = __shfl_up_sync(FULL, a_, dd);
        float bv = __shfl_up_sync(FULL, b_, dd);
        if (lane >= dd) { b_ = fmaf(bv, a_, b_); a_ = av * a_; }
    }
    float aex = __shfl_up_sync(FULL, a_, 1);
    float bex = __shfl_up_sync(FULL, b_, 1);
    if (lane == 0) { aex = 1.f; bex = 0.f; }
    float ppeS = fmaf(aex, s0ppe, bex);

    // ---- chunk-boundary lagged ar/inv/ap ----
    float pr1 = __shfl_up_sync(FULL, tr[7][1], 1);
    float pr5 = __shfl_up_sync(FULL, tr[7][5], 1);
    float pr6 = __shfl_up_sync(FULL, tr[7][6], 1);
    float pr7 = __shfl_up_sync(FULL, tr[7][7], 1);
    float arP, invP, apP;
    if (lane == 0) { arP = s0ar; invP = s0inv; apP = s0ap; }
    else {
        float cogsP = pr1 * revS;
        arP = pr5 * revS; invP = pr6 * cogsP; apP = pr7 * cogsP;
    }

    // ---- phase 3: chunk sums of cash & re increments ----
    float Cs = 0.f, Rs = 0.f;
    {
        float ppeP = ppeS, arp = arP, invp = invP, app = apP;
#pragma unroll
        for (int k = 0; k < 8; k++) {
            if (k < n) {
                float nrev = rev[k];
                float cogs = tr[k][1] * nrev;
                float opex = tr[k][2] * nrev;
                float dep  = tr[k][3] * ppeP;
                float intr = tr[k][9] * debt;
                float ebt  = nrev - cogs - opex - dep - intr;
                float tax  = tr[k][8] * fmaxf(ebt, 0.f);
                float ni   = ebt - tax;
                float arn  = tr[k][5] * nrev;
                float invn = tr[k][6] * cogs;
                float apn  = tr[k][7] * cogs;
                float capex = tr[k][4] * nrev;
                float cinc = ni + dep - capex - (arn - arp) - (invn - invp) + (apn - app);
                Cs += cinc; Rs += ni;
                ppeP = ppeP + capex - dep;
                arp = arn; invp = invn; app = apn;
            }
        }
    }
    float c = Cs;
#pragma unroll
    for (int dd = 1; dd < 32; dd <<= 1) {
        float v = __shfl_up_sync(FULL, c, dd);
        if (lane >= dd) c += v;
    }
    float ce = __shfl_up_sync(FULL, c, 1);
    if (lane == 0) ce = 0.f;
    float cashS = s0cash + ce;

    float rr = Rs;
#pragma unroll
    for (int dd = 1; dd < 32; dd <<= 1) {
        float v = __shfl_up_sync(FULL, rr, dd);
        if (lane >= dd) rr += v;
    }
    float re_e = __shfl_up_sync(FULL, rr, 1);
    if (lane == 0) re_e = 0.f;
    float reS = s0re + re_e;

    // ---- phase 4a: states walk -> skewed smem ----
    {
        float* sw = sbuf + w * STG_W;
        float cash = cashS, re = reS;
        float ppeP = ppeS, arp = arP, invp = invP, app = apP;
#pragma unroll
        for (int k = 0; k < 8; k++) {
            if (k < n) {
                float nrev = rev[k];
                float cogs = tr[k][1] * nrev;
                float opex = tr[k][2] * nrev;
                float dep  = tr[k][3] * ppeP;
                float intr = tr[k][9] * debt;
                float ebt  = nrev - cogs - opex - dep - intr;
                float tax  = tr[k][8] * fmaxf(ebt, 0.f);
                float ni   = ebt - tax;
                float arn  = tr[k][5] * nrev;
                float invn = tr[k][6] * cogs;
                float apn  = tr[k][7] * cogs;
                float capex = tr[k][4] * nrev;
                float ppen = ppeP + capex - dep;
                float cinc = ni + dep - capex - (arn - arp) - (invn - invp) + (apn - app);
                cash += cinc; re += ni;

                int idx = (o0 + k) * S_;
                sw[SKW(idx + 0)] = nrev;  sw[SKW(idx + 1)] = cash;
                sw[SKW(idx + 2)] = arn;   sw[SKW(idx + 3)] = invn;
                sw[SKW(idx + 4)] = ppen;  sw[SKW(idx + 5)] = apn;
                sw[SKW(idx + 6)] = debt;  sw[SKW(idx + 7)] = eqty;
                sw[SKW(idx + 8)] = re;    sw[SKW(idx + 9)] = oth;

                ppeP = ppen; arp = arn; invp = invn; app = apn;
            }
        }
    }
    __syncthreads();

    {
        int tid = threadIdx.x;
#pragma unroll
        for (int w2 = 0; w2 < 4; w2++) {
            const float* s = sbuf + w2 * STG_W;
            float* g = out + (long)(blockIdx.x * 4 + w2) * TO_ * S_;
            for (int i = tid; i < TO_ * S_; i += 128)
                g[i] = s[SKW(i)];
        }
    }
    __syncthreads();

    // ---- phase 4b: is walk -> skewed smem (reuse buffer) ----
    {
        float* sw = sbuf + w * ISG_W;
        float ppeP = ppeS, arp = arP, invp = invP, app = apP;
#pragma unroll
        for (int k = 0; k < 8; k++) {
            if (k < n) {
                float nrev = rev[k];
                float cogs = tr[k][1] * nrev;
                float opex = tr[k][2] * nrev;
                float dep  = tr[k][3] * ppeP;
                float intr = tr[k][9] * debt;
                float ebt  = nrev - cogs - opex - dep - intr;
                float tax  = tr[k][8] * fmaxf(ebt, 0.f);
                float ni   = ebt - tax;
                float capex = tr[k][4] * nrev;

                int idx = (o0 + k) * 7;
                sw[SKW(idx + 0)] = nrev;  sw[SKW(idx + 1)] = cogs;
                sw[SKW(idx + 2)] = opex;  sw[SKW(idx + 3)] = dep;
                sw[SKW(idx + 4)] = intr;  sw[SKW(idx + 5)] = tax;
                sw[SKW(idx + 6)] = ni;

                ppeP = ppeP + capex - dep;
                arp = tr[k][5] * nrev; invp = tr[k][6] * cogs; app = tr[k][7] * cogs;
            }
        }
    }
    __syncthreads();

    {
        int tid = threadIdx.x;
        float* ob = out + (long)B_ * TO_ * S_;
#pragma unroll
        for (int w2 = 0; w2 < 4; w2++) {
            const float* s = sbuf + w2 * ISG_W;
            float* g = ob + (long)(blockIdx.x * 4 + w2) * TO_ * 7;
            for (int i = tid; i < TO_ * 7; i += 128)
                g[i] = s[SKW(i)];
        }
    }
}

extern "C" void kernel_launch(void* const* d_in, const int* in_sizes, int n_in,
                              void* d_out, int out_size)
{
    const float* states = (const float*)d_in[0];
    const float* cov    = (const float*)d_in[1];
    const float* gamma  = (const float*)d_in[2];
    const float* beta   = (const float*)d_in[3];
    const float* wx     = (const float*)d_in[4];
    const float* wh     = (const float*)d_in[5];
    const float* rnn_b  = (const float*)d_in[6];
    const float* d1w    = (const float*)d_in[7];
    const float* d1b    = (const float*)d_in[8];
    const float* d2w    = (const float*)d_in[9];
    const float* d2b    = (const float*)d_in[10];
    float* out = (float*)d_out;

    k_ln_xw<<<(B_ * T_ / 4) / 256, 256>>>(cov, gamma, beta, wx, rnn_b);
    k_rnn<<<B_ / 8, 128>>>(wh);
    k_mlp<<<(B_ * T_) / 256, 256>>>(d1w, d1b, d2w, d2b);
    k_cash<<<B_ / 4, 128>>>(states, out);
}

// round 13
// speedup vs baseline: 1.1631x; 1.0698x over previous
#include <cuda_runtime.h>

#define B_ 4096
#define T_ 256
#define C_ 64
#define H_ 16
#define D_ 16
#define S_ 10
#define TO_ 255

// PLANAR xw: plane j at g_xw[j*B*T + b*T + t]  (lane streams contiguous in t)
__device__ float g_xw[(long)H_ * B_ * T_];
__device__ float g_hs[(long)B_ * T_ * H_];   // RNN hidden states, row-major [r][16]
// PLANAR tr: plane j at g_tr[j*B*T + b*T + (t-1)], t in [1,256)
__device__ float g_tr[(long)10 * B_ * T_];

// ---- fast transcendentals ----
__device__ __forceinline__ float fex2(float x) {
    float r; asm("ex2.approx.f32 %0, %1;" : "=f"(r) : "f"(x)); return r;
}
__device__ __forceinline__ float frcp(float x) {
    float r; asm("rcp.approx.f32 %0, %1;" : "=f"(r) : "f"(x)); return r;
}
__device__ __forceinline__ float fsig(float x) {
    return frcp(1.0f + fex2(-1.4426950408889634f * x));
}
__device__ __forceinline__ float ftanh(float x) {
    return fmaf(2.0f, frcp(1.0f + fex2(-2.8853900817779268f * x)), -1.0f);
}

// ---------------------------------------------------------------------------
// Kernel 1: fused LayerNorm + x@Wx + b (LN folded). 4 rows per thread,
// software-pipelined cov loads (prefetch distance 1). Planar output.
// ---------------------------------------------------------------------------
__global__ void __launch_bounds__(256) k_ln_xw(
    const float* __restrict__ cov,
    const float* __restrict__ gamma,
    const float* __restrict__ beta,
    const float* __restrict__ wx,
    const float* __restrict__ rnn_b)
{
    __shared__ float sWg[C_ * H_];
    __shared__ float sS1[H_];
    __shared__ float sS2[H_];

    int tid = threadIdx.x;
    for (int i = tid; i < C_ * H_; i += blockDim.x) {
        int c = i >> 4;
        sWg[i] = gamma[c] * wx[i];
    }
    __syncthreads();
    if (tid < H_) {
        float s1 = 0.f, s2 = 0.f;
        for (int c = 0; c < C_; c++) {
            s1 += sWg[c * H_ + tid];
            s2 += beta[c] * wx[c * H_ + tid];
        }
        sS1[tid] = s1;
        sS2[tid] = s2 + rnn_b[tid];
    }
    __syncthreads();

    const float4* wg4 = reinterpret_cast<const float4*>(sWg);

    const long Q = (long)B_ * T_ / 4;
    const long BT = (long)B_ * T_;
    long r = (long)blockIdx.x * blockDim.x + tid;

    const float4* cv[4];
#pragma unroll
    for (int s = 0; s < 4; s++)
        cv[s] = reinterpret_cast<const float4*>(cov + (r + s * Q) * C_);

    float acc[4][H_];
#pragma unroll
    for (int s = 0; s < 4; s++)
#pragma unroll
        for (int j = 0; j < H_; j++) acc[s][j] = 0.f;
    float sum[4] = {0.f, 0.f, 0.f, 0.f};
    float sq[4]  = {0.f, 0.f, 0.f, 0.f};

    // software pipeline: prefetch distance 1
    float4 cur[4], nxt[4];
#pragma unroll
    for (int s = 0; s < 4; s++) cur[s] = cv[s][0];

    for (int c4 = 0; c4 < C_ / 4; c4++) {
        if (c4 + 1 < C_ / 4) {
#pragma unroll
            for (int s = 0; s < 4; s++) nxt[s] = cv[s][c4 + 1];
        }
        float xs[4][4];
#pragma unroll
        for (int s = 0; s < 4; s++) {
            xs[s][0] = cur[s].x; xs[s][1] = cur[s].y;
            xs[s][2] = cur[s].z; xs[s][3] = cur[s].w;
        }
#pragma unroll
        for (int k = 0; k < 4; k++) {
            int c = c4 * 4 + k;
            float4 w0 = wg4[c * 4 + 0];
            float4 w1 = wg4[c * 4 + 1];
            float4 w2 = wg4[c * 4 + 2];
            float4 w3 = wg4[c * 4 + 3];
#pragma unroll
            for (int s = 0; s < 4; s++) {
                float x = xs[s][k];
                sum[s] += x;
                sq[s] = fmaf(x, x, sq[s]);
                acc[s][0]  += x * w0.x; acc[s][1]  += x * w0.y;
                acc[s][2]  += x * w0.z; acc[s][3]  += x * w0.w;
                acc[s][4]  += x * w1.x; acc[s][5]  += x * w1.y;
                acc[s][6]  += x * w1.z; acc[s][7]  += x * w1.w;
                acc[s][8]  += x * w2.x; acc[s][9]  += x * w2.y;
                acc[s][10] += x * w2.z; acc[s][11] += x * w2.w;
                acc[s][12] += x * w3.x; acc[s][13] += x * w3.y;
                acc[s][14] += x * w3.z; acc[s][15] += x * w3.w;
            }
        }
#pragma unroll
        for (int s = 0; s < 4; s++) cur[s] = nxt[s];
    }

#pragma unroll
    for (int s = 0; s < 4; s++) {
        float mu = sum[s] * (1.f/64.f);
        float rs = rsqrtf(sq[s] * (1.f/64.f) - mu*mu + 1e-3f);
        float rm = rs * mu;
        long rr = r + s * Q;
#pragma unroll
        for (int j = 0; j < H_; j++)
            g_xw[j * BT + rr] = rs * acc[s][j] - rm * sS1[j] + sS2[j];
    }
}

// ---------------------------------------------------------------------------
// Kernel 2: RNN recurrence. 16-lane team per batch, 2 teams/warp.
// h broadcast via double-buffered SMEM (1 STS + 4 broadcast LDS.128 per step
// instead of 16 SHFL) — removes the SHFL MIO-throughput bottleneck.
// xw streamed planar, 8 steps per two float4 loads, double-buffered.
// ---------------------------------------------------------------------------
__global__ void __launch_bounds__(128) k_rnn(const float* __restrict__ wh)
{
    __shared__ float sh[2][8][H_];   // [parity][team][component]

    int tid = threadIdx.x;
    int q = tid & 15;
    int team = tid >> 4;             // 0..7 within block
    int b = blockIdx.x * 8 + team;

    float whc[H_];
#pragma unroll
    for (int i = 0; i < H_; i++) whc[i] = wh[i * H_ + q];

    const long BT = (long)B_ * T_;
    const float4* xp = reinterpret_cast<const float4*>(g_xw + (long)q * BT + (long)b * T_);
    float* hsp = g_hs + (long)b * T_ * H_;

    float h = 0.f;
    float4 c0 = xp[0], c1 = xp[1];

    for (int t8 = 0; t8 < T_ / 8; t8++) {
        float4 n0, n1;
        if (t8 + 1 < T_ / 8) {
            n0 = xp[(t8 + 1) * 2];
            n1 = xp[(t8 + 1) * 2 + 1];
        } else {
            n0 = make_float4(0.f, 0.f, 0.f, 0.f);
            n1 = n0;
        }
        float xw8[8] = {c0.x, c0.y, c0.z, c0.w, c1.x, c1.y, c1.z, c1.w};
#pragma unroll
        for (int u = 0; u < 8; u++) {
            int pb = u & 1;
            sh[pb][team][q] = h;
            __syncwarp();
            const float4* hv = reinterpret_cast<const float4*>(sh[pb][team]);
            float4 h0 = hv[0], h1 = hv[1], h2 = hv[2], h3 = hv[3];

            float a0 = xw8[u], a1 = 0.f, a2 = 0.f, a3 = 0.f;
            a0 = fmaf(h0.x, whc[0],  a0);
            a1 = fmaf(h0.y, whc[1],  a1);
            a2 = fmaf(h0.z, whc[2],  a2);
            a3 = fmaf(h0.w, whc[3],  a3);
            a0 = fmaf(h1.x, whc[4],  a0);
            a1 = fmaf(h1.y, whc[5],  a1);
            a2 = fmaf(h1.z, whc[6],  a2);
            a3 = fmaf(h1.w, whc[7],  a3);
            a0 = fmaf(h2.x, whc[8],  a0);
            a1 = fmaf(h2.y, whc[9],  a1);
            a2 = fmaf(h2.z, whc[10], a2);
            a3 = fmaf(h2.w, whc[11], a3);
            a0 = fmaf(h3.x, whc[12], a0);
            a1 = fmaf(h3.y, whc[13], a1);
            a2 = fmaf(h3.z, whc[14], a2);
            a3 = fmaf(h3.w, whc[15], a3);

            h = ftanh((a0 + a1) + (a2 + a3));
            hsp[(t8 * 8 + u) * H_ + q] = h;
        }
        c0 = n0; c1 = n1;
    }
}

// ---------------------------------------------------------------------------
// Kernel 3: batched driver MLP + transforms. Planar coalesced output.
// ---------------------------------------------------------------------------
__global__ void __launch_bounds__(256) k_mlp(
    const float* __restrict__ d1w,
    const float* __restrict__ d1b,
    const float* __restrict__ d2w,
    const float* __restrict__ d2b)
{
    __shared__ float sw1[H_ * H_];
    __shared__ float sw2[H_ * 10];
    __shared__ float sb1[H_];
    __shared__ float sb2[10];

    int tid = threadIdx.x;
    if (tid < H_ * H_) sw1[tid] = d1w[tid];
    if (tid < H_ * 10) { int i = tid / 10, j = tid % 10; sw2[tid] = d2w[i * D_ + j]; }
    if (tid < H_) sb1[tid] = d1b[tid];
    if (tid < 10) sb2[tid] = d2b[tid];
    __syncthreads();

    long r = (long)blockIdx.x * blockDim.x + tid;
    int t = (int)(r & (T_ - 1));
    if (t == 0) return;   // drivers for t=0 unused

    const float4* hp = reinterpret_cast<const float4*>(g_hs + r * H_);
    float4 h4[4] = {hp[0], hp[1], hp[2], hp[3]};
    const float* hv = reinterpret_cast<const float*>(h4);

    const float4* w14 = reinterpret_cast<const float4*>(sw1);
    float a[H_];
#pragma unroll
    for (int j = 0; j < H_; j++) a[j] = sb1[j];
#pragma unroll
    for (int i = 0; i < H_; i++) {
        float xi = hv[i];
        float4 w0 = w14[i * 4 + 0];
        float4 w1 = w14[i * 4 + 1];
        float4 w2 = w14[i * 4 + 2];
        float4 w3 = w14[i * 4 + 3];
        a[0]  += xi * w0.x; a[1]  += xi * w0.y; a[2]  += xi * w0.z; a[3]  += xi * w0.w;
        a[4]  += xi * w1.x; a[5]  += xi * w1.y; a[6]  += xi * w1.z; a[7]  += xi * w1.w;
        a[8]  += xi * w2.x; a[9]  += xi * w2.y; a[10] += xi * w2.z; a[11] += xi * w2.w;
        a[12] += xi * w3.x; a[13] += xi * w3.y; a[14] += xi * w3.z; a[15] += xi * w3.w;
    }
#pragma unroll
    for (int j = 0; j < H_; j++) a[j] = ftanh(a[j]);

    float d[10];
#pragma unroll
    for (int j = 0; j < 10; j++) d[j] = sb2[j];
#pragma unroll
    for (int i = 0; i < H_; i++) {
        float xi = a[i];
        const float2* w2r = reinterpret_cast<const float2*>(sw2 + i * 10);
#pragma unroll
        for (int j2 = 0; j2 < 5; j2++) {
            float2 w = w2r[j2];
            d[j2 * 2]     += xi * w.x;
            d[j2 * 2 + 1] += xi * w.y;
        }
    }

    const long BT = (long)B_ * T_;
    float* p = g_tr + (r - 1);     // stored at index t-1 within batch row
    p[0 * BT] = fsig(2.0f * d[0]) * 0.4f - 0.2f;   // tanh(d0)*0.2
    p[1 * BT] = fsig(d[1]);
    p[2 * BT] = fsig(d[2]) * 0.5f;
    p[3 * BT] = fsig(d[3]) * 0.1f;
    p[4 * BT] = fsig(d[4]) * 0.2f;
    p[5 * BT] = fsig(d[5]);
    p[6 * BT] = fsig(d[6]);
    p[7 * BT] = fsig(d[7]);
    p[8 * BT] = fsig(d[8]) * 0.35f;
    p[9 * BT] = fsig(d[9]) * 0.1f;
}

// ---------------------------------------------------------------------------
// Kernel 4: cash-budget scan. T-parallel, one warp per batch.
// ---------------------------------------------------------------------------
#define SKW(i) ((i) + ((i) >> 5))
#define STG_W 2632
#define ISG_W 1844

__global__ void __launch_bounds__(128) k_cash(
    const float* __restrict__ states_seq,
    float* __restrict__ out)
{
    __shared__ float sbuf[4 * STG_W];   // 42 KB, reused for both passes

    const unsigned FULL = 0xffffffffu;
    int lane = threadIdx.x & 31;
    int w = threadIdx.x >> 5;
    int b = blockIdx.x * 4 + w;
    int o0 = lane * 8;
    int n = (lane == 31) ? 7 : 8;

    const float* s0 = states_seq + (long)b * T_ * S_;
    float s0rev = s0[0], s0cash = s0[1], s0ar = s0[2], s0inv = s0[3], s0ppe = s0[4],
          s0ap  = s0[5], debt = s0[6], eqty = s0[7], s0re = s0[8], oth = s0[9];

    const long BT = (long)B_ * T_;
    float tr[8][10];
    {
        const float* base = g_tr + (long)b * T_ + o0;
#pragma unroll
        for (int j = 0; j < 10; j++) {
            float4 v0 = *reinterpret_cast<const float4*>(base + j * BT);
            float4 v1 = *reinterpret_cast<const float4*>(base + j * BT + 4);
            tr[0][j] = v0.x; tr[1][j] = v0.y; tr[2][j] = v0.z; tr[3][j] = v0.w;
            tr[4][j] = v1.x; tr[5][j] = v1.y; tr[6][j] = v1.z; tr[7][j] = v1.w;
        }
    }

    // ---- phase 1: revenue product scan ----
    float Pg = 1.f;
#pragma unroll
    for (int k = 0; k < 8; k++) if (k < n) Pg *= (1.f + tr[k][0]);
    float p = Pg;
#pragma unroll
    for (int dd = 1; dd < 32; dd <<= 1) {
        float v = __shfl_up_sync(FULL, p, dd);
        if (lane >= dd) p *= v;
    }
    float pe = __shfl_up_sync(FULL, p, 1);
    if (lane == 0) pe = 1.f;
    float revS = s0rev * pe;

    // ---- phase 2: rev stepwise + ppe affine scan ----
    float rev[8];
    float A = 1.f, Bc = 0.f, rprev = revS;
#pragma unroll
    for (int k = 0; k < 8; k++) {
        if (k < n) {
            rprev *= (1.f + tr[k][0]);
            rev[k] = rprev;
            float om = 1.f - tr[k][3];
            A = A * om;
            Bc = fmaf(Bc, om, tr[k][4] * rprev);
        } else rev[k] = rprev;
    }
    float a_ = A, b_ = Bc;
#pragma unroll
    for (int dd = 1; dd < 32; dd <<= 1) {
        float av = __shfl_up_sync(FULL, a_, dd);
        float bv = __shfl_up_sync(FULL, b_, dd);
        if (lane >= dd) { b_ = fmaf(bv, a_, b_); a_ = av * a_; }
    }
    float aex = __shfl_up_sync(FULL, a_, 1);
    float bex = __shfl_up_sync(FULL, b_, 1);
    if (lane == 0) { aex = 1.f; bex = 0.f; }
    float ppeS = fmaf(aex, s0ppe, bex);

    // ---- chunk-boundary lagged ar/inv/ap ----
    float pr1 = __shfl_up_sync(FULL, tr[7][1], 1);
    float pr5 = __shfl_up_sync(FULL, tr[7][5], 1);
    float pr6 = __shfl_up_sync(FULL, tr[7][6], 1);
    float pr7 = __shfl_up_sync(FULL, tr[7][7], 1);
    float arP, invP, apP;
    if (lane == 0) { arP = s0ar; invP = s0inv; apP = s0ap; }
    else {
        float cogsP = pr1 * revS;
        arP = pr5 * revS; invP = pr6 * cogsP; apP = pr7 * cogsP;
    }

    // ---- phase 3: chunk sums of cash & re increments ----
    float Cs = 0.f, Rs = 0.f;
    {
        float ppeP = ppeS, arp = arP, invp = invP, app = apP;
#pragma unroll
        for (int k = 0; k < 8; k++) {
            if (k < n) {
                float nrev = rev[k];
                float cogs = tr[k][1] * nrev;
                float opex = tr[k][2] * nrev;
                float dep  = tr[k][3] * ppeP;
                float intr = tr[k][9] * debt;
                float ebt  = nrev - cogs - opex - dep - intr;
                float tax  = tr[k][8] * fmaxf(ebt, 0.f);
                float ni   = ebt - tax;
                float arn  = tr[k][5] * nrev;
                float invn = tr[k][6] * cogs;
                float apn  = tr[k][7] * cogs;
                float capex = tr[k][4] * nrev;
                float cinc = ni + dep - capex - (arn - arp) - (invn - invp) + (apn - app);
                Cs += cinc; Rs += ni;
                ppeP = ppeP + capex - dep;
                arp = arn; invp = invn; app = apn;
            }
        }
    }
    float c = Cs;
#pragma unroll
    for (int dd = 1; dd < 32; dd <<= 1) {
        float v = __shfl_up_sync(FULL, c, dd);
        if (lane >= dd) c += v;
    }
    float ce = __shfl_up_sync(FULL, c, 1);
    if (lane == 0) ce = 0.f;
    float cashS = s0cash + ce;

    float rr = Rs;
#pragma unroll
    for (int dd = 1; dd < 32; dd <<= 1) {
        float v = __shfl_up_sync(FULL, rr, dd);
        if (lane >= dd) rr += v;
    }
    float re_e = __shfl_up_sync(FULL, rr, 1);
    if (lane == 0) re_e = 0.f;
    float reS = s0re + re_e;

    // ---- phase 4a: states walk -> skewed smem ----
    {
        float* sw = sbuf + w * STG_W;
        float cash = cashS, re = reS;
        float ppeP = ppeS, arp = arP, invp = invP, app = apP;
#pragma unroll
        for (int k = 0; k < 8; k++) {
            if (k < n) {
                float nrev = rev[k];
                float cogs = tr[k][1] * nrev;
                float opex = tr[k][2] * nrev;
                float dep  = tr[k][3] * ppeP;
                float intr = tr[k][9] * debt;
                float ebt  = nrev - cogs - opex - dep - intr;
                float tax  = tr[k][8] * fmaxf(ebt, 0.f);
                float ni   = ebt - tax;
                float arn  = tr[k][5] * nrev;
                float invn = tr[k][6] * cogs;
                float apn  = tr[k][7] * cogs;
                float capex = tr[k][4] * nrev;
                float ppen = ppeP + capex - dep;
                float cinc = ni + dep - capex - (arn - arp) - (invn - invp) + (apn - app);
                cash += cinc; re += ni;

                int idx = (o0 + k) * S_;
                sw[SKW(idx + 0)] = nrev;  sw[SKW(idx + 1)] = cash;
                sw[SKW(idx + 2)] = arn;   sw[SKW(idx + 3)] = invn;
                sw[SKW(idx + 4)] = ppen;  sw[SKW(idx + 5)] = apn;
                sw[SKW(idx + 6)] = debt;  sw[SKW(idx + 7)] = eqty;
                sw[SKW(idx + 8)] = re;    sw[SKW(idx + 9)] = oth;

                ppeP = ppen; arp = arn; invp = invn; app = apn;
            }
        }
    }
    __syncthreads();

    {
        int tid = threadIdx.x;
#pragma unroll
        for (int w2 = 0; w2 < 4; w2++) {
            const float* s = sbuf + w2 * STG_W;
            float* g = out + (long)(blockIdx.x * 4 + w2) * TO_ * S_;
            for (int i = tid; i < TO_ * S_; i += 128)
                g[i] = s[SKW(i)];
        }
    }
    __syncthreads();

    // ---- phase 4b: is walk -> skewed smem (reuse buffer) ----
    {
        float* sw = sbuf + w * ISG_W;
        float ppeP = ppeS, arp = arP, invp = invP, app = apP;
#pragma unroll
        for (int k = 0; k < 8; k++) {
            if (k < n) {
                float nrev = rev[k];
                float cogs = tr[k][1] * nrev;
                float opex = tr[k][2] * nrev;
                float dep  = tr[k][3] * ppeP;
                float intr = tr[k][9] * debt;
                float ebt  = nrev - cogs - opex - dep - intr;
                float tax  = tr[k][8] * fmaxf(ebt, 0.f);
                float ni   = ebt - tax;
                float capex = tr[k][4] * nrev;

                int idx = (o0 + k) * 7;
                sw[SKW(idx + 0)] = nrev;  sw[SKW(idx + 1)] = cogs;
                sw[SKW(idx + 2)] = opex;  sw[SKW(idx + 3)] = dep;
                sw[SKW(idx + 4)] = intr;  sw[SKW(idx + 5)] = tax;
                sw[SKW(idx + 6)] = ni;

                ppeP = ppeP + capex - dep;
                arp = tr[k][5] * nrev; invp = tr[k][6] * cogs; app = tr[k][7] * cogs;
            }
        }
    }
    __syncthreads();

    {
        int tid = threadIdx.x;
        float* ob = out + (long)B_ * TO_ * S_;
#pragma unroll
        for (int w2 = 0; w2 < 4; w2++) {
            const float* s = sbuf + w2 * ISG_W;
            float* g = ob + (long)(blockIdx.x * 4 + w2) * TO_ * 7;
            for (int i = tid; i < TO_ * 7; i += 128)
                g[i] = s[SKW(i)];
        }
    }
}

extern "C" void kernel_launch(void* const* d_in, const int* in_sizes, int n_in,
                              void* d_out, int out_size)
{
    const float* states = (const float*)d_in[0];
    const float* cov    = (const float*)d_in[1];
    const float* gamma  = (const float*)d_in[2];
    const float* beta   = (const float*)d_in[3];
    const float* wx     = (const float*)d_in[4];
    const float* wh     = (const float*)d_in[5];
    const float* rnn_b  = (const float*)d_in[6];
    const float* d1w    = (const float*)d_in[7];
    const float* d1b    = (const float*)d_in[8];
    const float* d2w    = (const float*)d_in[9];
    const float* d2b    = (const float*)d_in[10];
    float* out = (float*)d_out;

    k_ln_xw<<<(B_ * T_ / 4) / 256, 256>>>(cov, gamma, beta, wx, rnn_b);
    k_rnn<<<B_ / 8, 128>>>(wh);
    k_mlp<<<(B_ * T_) / 256, 256>>>(d1w, d1b, d2w, d2b);
    k_cash<<<B_ / 4, 128>>>(states, out);
}